// round 1
// baseline (speedup 1.0000x reference)
#include <cuda_runtime.h>

// ---------------------------------------------------------------------------
// Scratch (static __device__ globals — no allocation allowed)
// ---------------------------------------------------------------------------
#define NCAP 1000000
#define FPAD 8   // padded feature stride for the pool-message array (float4-friendly)

__device__ float d_m[NCAP * FPAD];   // pool messages (layer 1 then layer 2), stride 8
__device__ float d_agg[NCAP * 5];    // segment-max accumulator (layer 1 then layer 2)
__device__ float d_h1[NCAP * 5];     // sigmoid(conv1 output)

__device__ __forceinline__ float sigm(float x) {
    return 1.0f / (1.0f + __expf(-x));
}

// ---------------------------------------------------------------------------
// Kernel 1: m1 = relu(x @ p1_W + p1_b); agg = 0
// ---------------------------------------------------------------------------
__global__ void node1_kernel(const float* __restrict__ x,
                             const float* __restrict__ W,
                             const float* __restrict__ b,
                             int N) {
    int i = blockIdx.x * blockDim.x + threadIdx.x;
    if (i >= N) return;
    float xv[5];
#pragma unroll
    for (int k = 0; k < 5; k++) xv[k] = x[i * 5 + k];
#pragma unroll
    for (int f = 0; f < 5; f++) {
        float acc = b[f];
#pragma unroll
        for (int k = 0; k < 5; k++) acc = fmaf(xv[k], W[k * 5 + f], acc);
        d_m[i * FPAD + f] = fmaxf(acc, 0.0f);
        d_agg[i * 5 + f] = 0.0f;
    }
}

// ---------------------------------------------------------------------------
// Edge scatter-max: agg[dst] = max(agg[dst], m[src]) per feature.
// relu output >= 0 so signed-int atomicMax on the float bits is exact.
// Pre-check load filters most atomics (stale reads are safe: values only grow).
// ---------------------------------------------------------------------------
__global__ void edge_kernel(const int* __restrict__ src,
                            const int* __restrict__ dst,
                            int E) {
    int i = blockIdx.x * blockDim.x + threadIdx.x;
    if (i >= E) return;
    int s = src[i];
    int d = dst[i];
    const float4* m4 = reinterpret_cast<const float4*>(d_m) + (size_t)s * 2;
    float4 a = m4[0];
    float v4 = d_m[(size_t)s * FPAD + 4];
    float vals[5] = {a.x, a.y, a.z, a.w, v4};
    int* ag = reinterpret_cast<int*>(d_agg) + (size_t)d * 5;
#pragma unroll
    for (int f = 0; f < 5; f++) {
        int vb = __float_as_int(vals[f]);
        if (vb > 0) {                 // skip zeros (relu) — agg starts at 0
            int cur = ag[f];          // possibly stale (smaller) -> safe filter
            if (vb > cur) atomicMax(ag + f, vb);
        }
    }
}

// ---------------------------------------------------------------------------
// Kernel 3: h1 = sigmoid(x @ s1_W + agg1 @ n1_W + b1)
//           m2 = relu(h1 @ p2_W + p2_b); agg = 0 (reused for layer 2)
// ---------------------------------------------------------------------------
__global__ void node2_kernel(const float* __restrict__ x,
                             const float* __restrict__ s1W,
                             const float* __restrict__ n1W,
                             const float* __restrict__ b1,
                             const float* __restrict__ p2W,
                             const float* __restrict__ p2b,
                             int N) {
    int i = blockIdx.x * blockDim.x + threadIdx.x;
    if (i >= N) return;
    float xv[5], av[5], h[5];
#pragma unroll
    for (int k = 0; k < 5; k++) {
        xv[k] = x[i * 5 + k];
        av[k] = d_agg[i * 5 + k];
    }
#pragma unroll
    for (int f = 0; f < 5; f++) {
        float acc = b1[f];
#pragma unroll
        for (int k = 0; k < 5; k++) acc = fmaf(xv[k], s1W[k * 5 + f], acc);
#pragma unroll
        for (int k = 0; k < 5; k++) acc = fmaf(av[k], n1W[k * 5 + f], acc);
        h[f] = sigm(acc);
        d_h1[i * 5 + f] = h[f];
    }
#pragma unroll
    for (int f = 0; f < 5; f++) {
        float acc = p2b[f];
#pragma unroll
        for (int k = 0; k < 5; k++) acc = fmaf(h[k], p2W[k * 5 + f], acc);
        d_m[i * FPAD + f] = fmaxf(acc, 0.0f);
        d_agg[i * 5 + f] = 0.0f;     // re-zero for layer-2 scatter
    }
}

// ---------------------------------------------------------------------------
// Kernel 5: leaf-only conv2 output + command product + 4-layer sigmoid MLP
// ---------------------------------------------------------------------------
__global__ __launch_bounds__(256) void leaf_kernel(
    const int* __restrict__ leaf, const float* __restrict__ cmd,
    const float* __restrict__ s2W, const float* __restrict__ n2W,
    const float* __restrict__ b2,
    const float* __restrict__ cmdW, const float* __restrict__ cmdb,
    const float* __restrict__ o1W, const float* __restrict__ o1b,
    const float* __restrict__ o2W, const float* __restrict__ o2b,
    const float* __restrict__ o3W, const float* __restrict__ o3b,
    const float* __restrict__ o4W, const float* __restrict__ o4b,
    float* __restrict__ out, int L) {

    __shared__ float S_s2W[50], S_n2W[50], S_b2[10], S_enc[10];
    __shared__ float S_o1W[320], S_o1b[32];
    __shared__ float S_o2W[1024], S_o2b[32];
    __shared__ float S_o3W[1024], S_o3b[32];
    __shared__ float S_o4W[32], S_o4b;

    int t = threadIdx.x;
    for (int k = t; k < 50; k += 256) { S_s2W[k] = s2W[k]; S_n2W[k] = n2W[k]; }
    for (int k = t; k < 320; k += 256) S_o1W[k] = o1W[k];
    for (int k = t; k < 1024; k += 256) { S_o2W[k] = o2W[k]; S_o3W[k] = o3W[k]; }
    if (t < 32) { S_o1b[t] = o1b[t]; S_o2b[t] = o2b[t]; S_o3b[t] = o3b[t]; S_o4W[t] = o4W[t]; }
    if (t < 10) {
        S_b2[t] = b2[t];
        S_enc[t] = cmdb[t] + cmd[0] * cmdW[t] + cmd[1] * cmdW[10 + t];
    }
    if (t == 0) S_o4b = o4b[0];
    __syncthreads();

    int j = blockIdx.x * 256 + t;
    if (j >= L) return;
    int node = leaf[j];

    float hv[5], av[5];
#pragma unroll
    for (int k = 0; k < 5; k++) {
        hv[k] = d_h1[(size_t)node * 5 + k];
        av[k] = d_agg[(size_t)node * 5 + k];
    }

    // h2 = h1 @ s2_W + agg2 @ n2_W + b2 ; prod = h2 * enc
    float p[10];
#pragma unroll
    for (int f = 0; f < 10; f++) {
        float acc = S_b2[f];
#pragma unroll
        for (int k = 0; k < 5; k++) acc = fmaf(hv[k], S_s2W[k * 10 + f], acc);
#pragma unroll
        for (int k = 0; k < 5; k++) acc = fmaf(av[k], S_n2W[k * 10 + f], acc);
        p[f] = acc * S_enc[f];
    }

    float z[32], z2[32];
#pragma unroll
    for (int f = 0; f < 32; f++) {
        float acc = S_o1b[f];
#pragma unroll
        for (int k = 0; k < 10; k++) acc = fmaf(p[k], S_o1W[k * 32 + f], acc);
        z[f] = sigm(acc);
    }
#pragma unroll
    for (int f = 0; f < 32; f++) {
        float acc = S_o2b[f];
#pragma unroll
        for (int k = 0; k < 32; k++) acc = fmaf(z[k], S_o2W[k * 32 + f], acc);
        z2[f] = sigm(acc);
    }
#pragma unroll
    for (int f = 0; f < 32; f++) {
        float acc = S_o3b[f];
#pragma unroll
        for (int k = 0; k < 32; k++) acc = fmaf(z2[k], S_o3W[k * 32 + f], acc);
        z[f] = sigm(acc);
    }
    float acc = S_o4b;
#pragma unroll
    for (int k = 0; k < 32; k++) acc = fmaf(z[k], S_o4W[k], acc);
    out[j] = sigm(acc);
}

// ---------------------------------------------------------------------------
// Launch
// ---------------------------------------------------------------------------
extern "C" void kernel_launch(void* const* d_in, const int* in_sizes, int n_in,
                              void* d_out, int out_size) {
    const float* x    = (const float*)d_in[0];
    const int*   src  = (const int*)d_in[1];
    const int*   dst  = (const int*)d_in[2];
    const int*   leaf = (const int*)d_in[3];
    const float* cmd  = (const float*)d_in[4];
    const float* p1W  = (const float*)d_in[5];
    const float* p1b  = (const float*)d_in[6];
    const float* s1W  = (const float*)d_in[7];
    const float* n1W  = (const float*)d_in[8];
    const float* b1   = (const float*)d_in[9];
    const float* p2W  = (const float*)d_in[10];
    const float* p2b  = (const float*)d_in[11];
    const float* s2W  = (const float*)d_in[12];
    const float* n2W  = (const float*)d_in[13];
    const float* b2   = (const float*)d_in[14];
    const float* cmdW = (const float*)d_in[15];
    const float* cmdb = (const float*)d_in[16];
    const float* o1W  = (const float*)d_in[17];
    const float* o1b  = (const float*)d_in[18];
    const float* o2W  = (const float*)d_in[19];
    const float* o2b  = (const float*)d_in[20];
    const float* o3W  = (const float*)d_in[21];
    const float* o3b  = (const float*)d_in[22];
    const float* o4W  = (const float*)d_in[23];
    const float* o4b  = (const float*)d_in[24];

    int N = in_sizes[0] / 5;
    int E = in_sizes[1];
    int L = in_sizes[3];

    int nb = (N + 255) / 256;
    int eb = (E + 255) / 256;
    int lb = (L + 255) / 256;

    node1_kernel<<<nb, 256>>>(x, p1W, p1b, N);
    edge_kernel<<<eb, 256>>>(src, dst, E);
    node2_kernel<<<nb, 256>>>(x, s1W, n1W, b1, p2W, p2b, N);
    edge_kernel<<<eb, 256>>>(src, dst, E);
    leaf_kernel<<<lb, 256>>>(leaf, cmd, s2W, n2W, b2, cmdW, cmdb,
                             o1W, o1b, o2W, o2b, o3W, o3b, o4W, o4b,
                             (float*)d_out, L);
}